// round 2
// baseline (speedup 1.0000x reference)
#include <cuda_runtime.h>
#include <stdint.h>

#define N_NODES 100000
#define N_EDGES 1600000
#define HID 256

// ---------------- scratch (device globals; no allocation allowed) ----------
__device__ float g_h[(size_t)N_NODES * HID];
__device__ float g_hw[(size_t)N_NODES * HID];
__device__ float g_agg[(size_t)N_NODES * HID];
__device__ float g_deg[N_NODES];
__device__ float g_dinv[N_NODES];
__device__ float g_self[N_NODES];
__device__ float g_c1[(size_t)N_NODES * 128];
__device__ float g_c2[(size_t)N_NODES * 64];
__device__ float g_c3[(size_t)N_NODES * 32];
__device__ int   g_src32[N_EDGES];
__device__ int   g_dst32[N_EDGES];
__device__ int   g_is64;

// ---------------- edge dtype detection + conversion -------------------------
// JAX with default config silently downcasts int64 -> int32. Detect layout:
// if edge data is int64 (values < 2^31), every odd int32 word is 0.
__global__ void detect_kernel(const int* __restrict__ e_raw, int n_check) {
    __shared__ int nz;
    if (threadIdx.x == 0) nz = 0;
    __syncthreads();
    for (int i = threadIdx.x; i < n_check; i += blockDim.x)
        if (e_raw[2 * i + 1] != 0) atomicAdd(&nz, 1);
    __syncthreads();
    if (threadIdx.x == 0) g_is64 = (nz == 0) ? 1 : 0;
}

__global__ void convert_kernel(const int* __restrict__ e_raw,
                               int* __restrict__ src32, int* __restrict__ dst32, int E) {
    int i = blockIdx.x * blockDim.x + threadIdx.x;
    if (i >= E) return;
    if (g_is64) {
        src32[i] = e_raw[2 * i];             // low word of edge[0][i]
        dst32[i] = e_raw[2 * (E + i)];       // low word of edge[1][i]
    } else {
        src32[i] = e_raw[i];
        dst32[i] = e_raw[E + i];
    }
}

// ---------------- degree / norm kernels ------------------------------------
__global__ void deg_init_kernel(float* deg, int n) {
    int i = blockIdx.x * blockDim.x + threadIdx.x;
    if (i < n) deg[i] = 1.0f;   // self-loop contribution
}

__global__ void deg_accum_kernel(const int* __restrict__ dst, float* deg, int e) {
    int i = blockIdx.x * blockDim.x + threadIdx.x;
    if (i < e) atomicAdd(&deg[dst[i]], 1.0f);
}

__global__ void norm_kernel(const float* __restrict__ deg,
                            float* __restrict__ dinv, float* __restrict__ selfw, int n) {
    int i = blockIdx.x * blockDim.x + threadIdx.x;
    if (i < n) {
        float d = deg[i];
        dinv[i]  = rsqrtf(d);
        selfw[i] = 1.0f / d;
    }
}

// ---------------- generic tiled GEMM: C = A(MxK) @ B(KxN) [+bias][ReLU] ----
template<int BM, int BN, int BK, int TM, int TN, bool RELU, bool BIAS>
__global__ void gemm_kernel(const float* __restrict__ A, const float* __restrict__ B,
                            const float* __restrict__ bias, float* __restrict__ C,
                            int M, int N, int K)
{
    constexpr int THREADS = (BM / TM) * (BN / TN);
    __shared__ float As[BK][BM];
    __shared__ float Bs[BK][BN];

    const int tid = threadIdx.x;
    const int tx  = tid % (BN / TN);
    const int ty  = tid / (BN / TN);
    const int row0 = blockIdx.y * BM;
    const int col0 = blockIdx.x * BN;

    float acc[TM][TN];
#pragma unroll
    for (int i = 0; i < TM; i++)
#pragma unroll
        for (int j = 0; j < TN; j++) acc[i][j] = 0.0f;

    for (int k0 = 0; k0 < K; k0 += BK) {
#pragma unroll 4
        for (int i = tid; i < BM * BK; i += THREADS) {
            int r = i / BK, c = i % BK;
            int gr = row0 + r, gc = k0 + c;
            As[c][r] = (gr < M && gc < K) ? A[(size_t)gr * K + gc] : 0.0f;
        }
#pragma unroll 4
        for (int i = tid; i < BK * BN; i += THREADS) {
            int r = i / BN, c = i % BN;
            int gk = k0 + r, gc = col0 + c;
            Bs[r][c] = (gk < K && gc < N) ? B[(size_t)gk * N + gc] : 0.0f;
        }
        __syncthreads();
#pragma unroll
        for (int kk = 0; kk < BK; kk++) {
            float a[TM], b[TN];
#pragma unroll
            for (int i = 0; i < TM; i++) a[i] = As[kk][ty * TM + i];
#pragma unroll
            for (int j = 0; j < TN; j++) b[j] = Bs[kk][tx * TN + j];
#pragma unroll
            for (int i = 0; i < TM; i++)
#pragma unroll
                for (int j = 0; j < TN; j++)
                    acc[i][j] = fmaf(a[i], b[j], acc[i][j]);
        }
        __syncthreads();
    }

#pragma unroll
    for (int i = 0; i < TM; i++) {
        int gr = row0 + ty * TM + i;
        if (gr >= M) continue;
#pragma unroll
        for (int j = 0; j < TN; j++) {
            int gc = col0 + tx * TN + j;
            if (gc >= N) continue;
            float v = acc[i][j];
            if (BIAS) v += bias[gc];
            if (RELU) v = fmaxf(v, 0.0f);
            C[(size_t)gr * N + gc] = v;
        }
    }
}

// ---------------- agg = hw * self_norm (vectorized) -------------------------
__global__ void selfinit_kernel(const float* __restrict__ hw, const float* __restrict__ selfw,
                                float* __restrict__ agg, int n4)
{
    int idx = blockIdx.x * blockDim.x + threadIdx.x;
    if (idx >= n4) return;
    int row = idx / (HID / 4);
    float s = __ldg(&selfw[row]);
    float4 v = reinterpret_cast<const float4*>(hw)[idx];
    v.x *= s; v.y *= s; v.z *= s; v.w *= s;
    reinterpret_cast<float4*>(agg)[idx] = v;
}

// ---------------- scatter: agg[dst] += hw[src] * dinv[src]*dinv[dst] --------
// One warp per edge. 256 floats/row = 64 float4 = 2 float4 per lane.
__global__ void scatter_kernel(const int* __restrict__ src,
                               const int* __restrict__ dst,
                               const float* __restrict__ dinv,
                               const float* __restrict__ hw,
                               float* __restrict__ agg, int E)
{
    int e = blockIdx.x * 8 + (threadIdx.x >> 5);
    if (e >= E) return;
    int lane = threadIdx.x & 31;
    int s = __ldg(&src[e]);
    int d = __ldg(&dst[e]);
    float w = __ldg(&dinv[s]) * __ldg(&dinv[d]);
    const float4* srow = reinterpret_cast<const float4*>(hw + (size_t)s * HID);
    float4*       drow = reinterpret_cast<float4*>(agg + (size_t)d * HID);
#pragma unroll
    for (int i = 0; i < 2; i++) {
        float4 v = __ldg(&srow[lane + 32 * i]);
        v.x *= w; v.y *= w; v.z *= w; v.w *= w;
        asm volatile("red.global.add.v4.f32 [%0], {%1,%2,%3,%4};"
                     :: "l"(drow + lane + 32 * i),
                        "f"(v.x), "f"(v.y), "f"(v.z), "f"(v.w)
                     : "memory");
    }
}

// ---------------- h += relu((agg + conv_b) * gamma + beta) ------------------
__global__ void epilogue_kernel(const float* __restrict__ agg, const float* __restrict__ cb,
                                const float* __restrict__ gamma, const float* __restrict__ beta,
                                float* __restrict__ h, int n4)
{
    int idx = blockIdx.x * blockDim.x + threadIdx.x;
    if (idx >= n4) return;
    int c4 = idx % (HID / 4);
    float4 a  = reinterpret_cast<const float4*>(agg)[idx];
    float4 b  = __ldg(&reinterpret_cast<const float4*>(cb)[c4]);
    float4 g  = __ldg(&reinterpret_cast<const float4*>(gamma)[c4]);
    float4 bt = __ldg(&reinterpret_cast<const float4*>(beta)[c4]);
    float4 hv = reinterpret_cast<float4*>(h)[idx];
    hv.x += fmaxf(fmaf(a.x + b.x, g.x, bt.x), 0.0f);
    hv.y += fmaxf(fmaf(a.y + b.y, g.y, bt.y), 0.0f);
    hv.z += fmaxf(fmaf(a.z + b.z, g.z, bt.z), 0.0f);
    hv.w += fmaxf(fmaf(a.w + b.w, g.w, bt.w), 0.0f);
    reinterpret_cast<float4*>(h)[idx] = hv;
}

// ---------------- host launcher ---------------------------------------------
static inline dim3 gemm_grid(int M, int N) {
    return dim3((N + 63) / 64, (M + 127) / 128);
}

template<bool RELU, bool BIAS>
static void launch_gemm(const float* A, const float* B, const float* bias, float* C,
                        int M, int N, int K) {
    gemm_kernel<128, 64, 16, 8, 4, RELU, BIAS><<<gemm_grid(M, N), 256>>>(A, B, bias, C, M, N, K);
}

extern "C" void kernel_launch(void* const* d_in, const int* in_sizes, int n_in,
                              void* d_out, int out_size)
{
    const float* x      = (const float*)d_in[0];
    const int*   e_raw  = (const int*)d_in[1];   // int32 or int64; detected on device
    const float* embW   = (const float*)d_in[2];
    const float* embB   = (const float*)d_in[3];
    const float* convW  = (const float*)d_in[4];
    const float* convB  = (const float*)d_in[5];
    const float* gamma  = (const float*)d_in[6];
    const float* beta   = (const float*)d_in[7];
    const float* W0 = (const float*)d_in[8];
    const float* b0 = (const float*)d_in[9];
    const float* W1 = (const float*)d_in[10];
    const float* b1 = (const float*)d_in[11];
    const float* W2 = (const float*)d_in[12];
    const float* b2 = (const float*)d_in[13];
    const float* W3 = (const float*)d_in[14];
    const float* b3 = (const float*)d_in[15];
    float* out = (float*)d_out;

    const int N = N_NODES;
    const int E = in_sizes[1] / 2;   // element count of edge_index / 2

    float *h, *hw, *agg, *deg, *dinv, *selfw, *c1, *c2, *c3;
    int *src32, *dst32;
    cudaGetSymbolAddress((void**)&h,     g_h);
    cudaGetSymbolAddress((void**)&hw,    g_hw);
    cudaGetSymbolAddress((void**)&agg,   g_agg);
    cudaGetSymbolAddress((void**)&deg,   g_deg);
    cudaGetSymbolAddress((void**)&dinv,  g_dinv);
    cudaGetSymbolAddress((void**)&selfw, g_self);
    cudaGetSymbolAddress((void**)&c1,    g_c1);
    cudaGetSymbolAddress((void**)&c2,    g_c2);
    cudaGetSymbolAddress((void**)&c3,    g_c3);
    cudaGetSymbolAddress((void**)&src32, g_src32);
    cudaGetSymbolAddress((void**)&dst32, g_dst32);

    // 0. edge dtype detection + conversion to int32 src/dst
    detect_kernel<<<1, 256>>>(e_raw, 1024);
    convert_kernel<<<(E + 255) / 256, 256>>>(e_raw, src32, dst32, E);

    // 1. degrees + norms
    deg_init_kernel<<<(N + 255) / 256, 256>>>(deg, N);
    deg_accum_kernel<<<(E + 255) / 256, 256>>>(dst32, deg, E);
    norm_kernel<<<(N + 255) / 256, 256>>>(deg, dinv, selfw, N);

    // 2. embed: h = x @ embW + embB   (100000 x 500 @ 500 x 256)
    launch_gemm<false, true>(x, embW, embB, h, N, HID, 500);

    const int n4 = N * HID / 4;
    const int ew_blocks = (n4 + 255) / 256;
    const int sc_blocks = (E + 7) / 8;

    // 3. GCN layers
    for (int l = 0; l < 3; l++) {
        const float* Wl  = convW + (size_t)l * HID * HID;
        const float* cbl = convB + (size_t)l * HID;
        const float* gl  = gamma + (size_t)l * HID;
        const float* btl = beta  + (size_t)l * HID;

        launch_gemm<false, false>(h, Wl, nullptr, hw, N, HID, HID);
        selfinit_kernel<<<ew_blocks, 256>>>(hw, selfw, agg, n4);
        scatter_kernel<<<sc_blocks, 256>>>(src32, dst32, dinv, hw, agg, E);
        epilogue_kernel<<<ew_blocks, 256>>>(agg, cbl, gl, btl, h, n4);
    }

    // 4. classifier MLP
    launch_gemm<true,  true>(h,  W0, b0, c1,  N, 128, 256);
    launch_gemm<true,  true>(c1, W1, b1, c2,  N, 64,  128);
    launch_gemm<true,  true>(c2, W2, b2, c3,  N, 32,  64);
    launch_gemm<false, true>(c3, W3, b3, out, N, 40,  32);
}

// round 3
// speedup vs baseline: 1.2942x; 1.2942x over previous
#include <cuda_runtime.h>
#include <stdint.h>

#define N_NODES 100000
#define N_EDGES 1600000
#define HID 256
#define SCAN_B 1024

// ---------------- scratch (device globals; no allocation allowed) ----------
__device__ float g_h[(size_t)N_NODES * HID];
__device__ float g_hw[(size_t)N_NODES * HID];
__device__ float g_deg[N_NODES];
__device__ float g_dinv[N_NODES];
__device__ float g_self[N_NODES];
__device__ float g_c1[(size_t)N_NODES * 128];
__device__ float g_c2[(size_t)N_NODES * 64];
__device__ float g_c3[(size_t)N_NODES * 32];
__device__ int   g_src32[N_EDGES];
__device__ int   g_dst32[N_EDGES];
__device__ int   g_cnt[N_NODES];
__device__ int   g_ptr[N_NODES + 1];
__device__ int   g_fill[N_NODES];
__device__ int   g_csr_src[N_EDGES];
__device__ float g_csr_w[N_EDGES];
__device__ int   g_bsum[(N_NODES + SCAN_B - 1) / SCAN_B + 1];
__device__ int   g_is64;

// ---------------- edge dtype detection + conversion -------------------------
__global__ void detect_kernel(const int* __restrict__ e_raw, int n_check) {
    __shared__ int nz;
    if (threadIdx.x == 0) nz = 0;
    __syncthreads();
    for (int i = threadIdx.x; i < n_check; i += blockDim.x)
        if (e_raw[2 * i + 1] != 0) atomicAdd(&nz, 1);
    __syncthreads();
    if (threadIdx.x == 0) g_is64 = (nz == 0) ? 1 : 0;
}

// convert + zero counters + count degrees in one pass
__global__ void convert_count_kernel(const int* __restrict__ e_raw,
                                     int* __restrict__ src32, int* __restrict__ dst32,
                                     int* __restrict__ cnt, int* __restrict__ fill, int E) {
    int i = blockIdx.x * blockDim.x + threadIdx.x;
    if (i < N_NODES) { cnt[i] = 0; fill[i] = 0; }   // E > N, covered
    if (i >= E) return;
    int s, d;
    if (g_is64) { s = e_raw[2 * i]; d = e_raw[2 * (E + i)]; }
    else        { s = e_raw[i];     d = e_raw[E + i]; }
    src32[i] = s;
    dst32[i] = d;
    atomicAdd(&cnt[d], 1);
}

__global__ void norm_kernel(const int* __restrict__ cnt,
                            float* __restrict__ dinv, float* __restrict__ selfw, int n) {
    int i = blockIdx.x * blockDim.x + threadIdx.x;
    if (i < n) {
        float d = (float)cnt[i] + 1.0f;   // self-loop
        dinv[i]  = rsqrtf(d);
        selfw[i] = 1.0f / d;
    }
}

// ---------------- exclusive scan of cnt -> ptr (3 kernels) ------------------
__global__ void scan1_kernel(const int* __restrict__ cnt, int* __restrict__ ptr,
                             int* __restrict__ bsum, int n) {
    __shared__ int sh[SCAN_B];
    int b = blockIdx.x;
    int i = b * SCAN_B + threadIdx.x;
    int v = (i < n) ? cnt[i] : 0;
    sh[threadIdx.x] = v;
    __syncthreads();
    // inclusive Hillis-Steele
    for (int off = 1; off < SCAN_B; off <<= 1) {
        int t = (threadIdx.x >= off) ? sh[threadIdx.x - off] : 0;
        __syncthreads();
        sh[threadIdx.x] += t;
        __syncthreads();
    }
    if (i <= n) {
        int ex = sh[threadIdx.x] - v;   // exclusive
        if (i < n) ptr[i] = ex;
    }
    if (threadIdx.x == SCAN_B - 1) bsum[b] = sh[SCAN_B - 1];
}

__global__ void scan2_kernel(int* __restrict__ bsum, int nb) {
    // single block exclusive scan of block sums (nb <= 128)
    __shared__ int sh[256];
    int v = (threadIdx.x < nb) ? bsum[threadIdx.x] : 0;
    sh[threadIdx.x] = v;
    __syncthreads();
    for (int off = 1; off < 256; off <<= 1) {
        int t = (threadIdx.x >= off) ? sh[threadIdx.x - off] : 0;
        __syncthreads();
        sh[threadIdx.x] += t;
        __syncthreads();
    }
    if (threadIdx.x < nb) bsum[threadIdx.x] = sh[threadIdx.x] - v;
}

__global__ void scan3_kernel(int* __restrict__ ptr, const int* __restrict__ bsum,
                             int n, int E) {
    int i = blockIdx.x * SCAN_B + threadIdx.x;
    if (i < n) ptr[i] += bsum[blockIdx.x];
    if (i == n) ptr[n] = E;
}

// ---------------- CSR fill with precomputed edge weight ---------------------
__global__ void csr_fill_kernel(const int* __restrict__ src, const int* __restrict__ dst,
                                const int* __restrict__ ptr, int* __restrict__ fill,
                                const float* __restrict__ dinv,
                                int* __restrict__ csr_src, float* __restrict__ csr_w, int E) {
    int i = blockIdx.x * blockDim.x + threadIdx.x;
    if (i >= E) return;
    int s = src[i], d = dst[i];
    int pos = atomicAdd(&fill[d], 1);
    int idx = ptr[d] + pos;
    csr_src[idx] = s;
    csr_w[idx] = dinv[s] * dinv[d];
}

// ---------------- generic tiled GEMM: C = A(MxK) @ B(KxN) [+bias][ReLU] ----
template<int BM, int BN, int BK, int TM, int TN, bool RELU, bool BIAS>
__global__ void gemm_kernel(const float* __restrict__ A, const float* __restrict__ B,
                            const float* __restrict__ bias, float* __restrict__ C,
                            int M, int N, int K)
{
    constexpr int THREADS = (BM / TM) * (BN / TN);
    __shared__ float As[BK][BM];
    __shared__ float Bs[BK][BN];

    const int tid = threadIdx.x;
    const int tx  = tid % (BN / TN);
    const int ty  = tid / (BN / TN);
    const int row0 = blockIdx.y * BM;
    const int col0 = blockIdx.x * BN;

    float acc[TM][TN];
#pragma unroll
    for (int i = 0; i < TM; i++)
#pragma unroll
        for (int j = 0; j < TN; j++) acc[i][j] = 0.0f;

    for (int k0 = 0; k0 < K; k0 += BK) {
#pragma unroll 4
        for (int i = tid; i < BM * BK; i += THREADS) {
            int r = i / BK, c = i % BK;
            int gr = row0 + r, gc = k0 + c;
            As[c][r] = (gr < M && gc < K) ? A[(size_t)gr * K + gc] : 0.0f;
        }
#pragma unroll 4
        for (int i = tid; i < BK * BN; i += THREADS) {
            int r = i / BN, c = i % BN;
            int gk = k0 + r, gc = col0 + c;
            Bs[r][c] = (gk < K && gc < N) ? B[(size_t)gk * N + gc] : 0.0f;
        }
        __syncthreads();
#pragma unroll
        for (int kk = 0; kk < BK; kk++) {
            float a[TM], b[TN];
#pragma unroll
            for (int i = 0; i < TM; i++) a[i] = As[kk][ty * TM + i];
#pragma unroll
            for (int j = 0; j < TN; j++) b[j] = Bs[kk][tx * TN + j];
#pragma unroll
            for (int i = 0; i < TM; i++)
#pragma unroll
                for (int j = 0; j < TN; j++)
                    acc[i][j] = fmaf(a[i], b[j], acc[i][j]);
        }
        __syncthreads();
    }

#pragma unroll
    for (int i = 0; i < TM; i++) {
        int gr = row0 + ty * TM + i;
        if (gr >= M) continue;
#pragma unroll
        for (int j = 0; j < TN; j++) {
            int gc = col0 + tx * TN + j;
            if (gc >= N) continue;
            float v = acc[i][j];
            if (BIAS) v += bias[gc];
            if (RELU) v = fmaxf(v, 0.0f);
            C[(size_t)gr * N + gc] = v;
        }
    }
}

// ---------------- fused aggregation + BN + ReLU + residual ------------------
// warp per destination node; lane covers float4 cols {lane, lane+32}
// h[d] += relu(((sum_j w_j*hw[src_j]) + selfw[d]*hw[d] + cb) * gamma + beta)
__global__ void agg_kernel(const int* __restrict__ ptr,
                           const int* __restrict__ csr_src,
                           const float* __restrict__ csr_w,
                           const float* __restrict__ selfw,
                           const float* __restrict__ hw,
                           const float* __restrict__ cb,
                           const float* __restrict__ gamma,
                           const float* __restrict__ beta,
                           float* __restrict__ h, int N)
{
    int d = blockIdx.x * 8 + (threadIdx.x >> 5);
    if (d >= N) return;
    int lane = threadIdx.x & 31;

    float4 a0 = make_float4(0.f, 0.f, 0.f, 0.f);
    float4 a1 = make_float4(0.f, 0.f, 0.f, 0.f);

    int beg = __ldg(&ptr[d]);
    int end = __ldg(&ptr[d + 1]);
#pragma unroll 2
    for (int j = beg; j < end; j++) {
        int s = __ldg(&csr_src[j]);
        float w = __ldg(&csr_w[j]);
        const float4* srow = reinterpret_cast<const float4*>(hw + (size_t)s * HID);
        float4 v0 = __ldg(&srow[lane]);
        float4 v1 = __ldg(&srow[lane + 32]);
        a0.x = fmaf(v0.x, w, a0.x); a0.y = fmaf(v0.y, w, a0.y);
        a0.z = fmaf(v0.z, w, a0.z); a0.w = fmaf(v0.w, w, a0.w);
        a1.x = fmaf(v1.x, w, a1.x); a1.y = fmaf(v1.y, w, a1.y);
        a1.z = fmaf(v1.z, w, a1.z); a1.w = fmaf(v1.w, w, a1.w);
    }

    // self loop
    float sw = __ldg(&selfw[d]);
    const float4* drow = reinterpret_cast<const float4*>(hw + (size_t)d * HID);
    float4 s0 = __ldg(&drow[lane]);
    float4 s1 = __ldg(&drow[lane + 32]);
    a0.x = fmaf(s0.x, sw, a0.x); a0.y = fmaf(s0.y, sw, a0.y);
    a0.z = fmaf(s0.z, sw, a0.z); a0.w = fmaf(s0.w, sw, a0.w);
    a1.x = fmaf(s1.x, sw, a1.x); a1.y = fmaf(s1.y, sw, a1.y);
    a1.z = fmaf(s1.z, sw, a1.z); a1.w = fmaf(s1.w, sw, a1.w);

    // epilogue
    const float4* cb4 = reinterpret_cast<const float4*>(cb);
    const float4* g4  = reinterpret_cast<const float4*>(gamma);
    const float4* bt4 = reinterpret_cast<const float4*>(beta);
    float4* hrow = reinterpret_cast<float4*>(h + (size_t)d * HID);

#pragma unroll
    for (int half = 0; half < 2; half++) {
        int c = lane + 32 * half;
        float4 a  = half ? a1 : a0;
        float4 b  = __ldg(&cb4[c]);
        float4 g  = __ldg(&g4[c]);
        float4 bt = __ldg(&bt4[c]);
        float4 hv = hrow[c];
        hv.x += fmaxf(fmaf(a.x + b.x, g.x, bt.x), 0.0f);
        hv.y += fmaxf(fmaf(a.y + b.y, g.y, bt.y), 0.0f);
        hv.z += fmaxf(fmaf(a.z + b.z, g.z, bt.z), 0.0f);
        hv.w += fmaxf(fmaf(a.w + b.w, g.w, bt.w), 0.0f);
        hrow[c] = hv;
    }
}

// ---------------- host launcher ---------------------------------------------
static inline dim3 gemm_grid(int M, int N) {
    return dim3((N + 63) / 64, (M + 127) / 128);
}

template<bool RELU, bool BIAS>
static void launch_gemm(const float* A, const float* B, const float* bias, float* C,
                        int M, int N, int K) {
    gemm_kernel<128, 64, 16, 8, 4, RELU, BIAS><<<gemm_grid(M, N), 256>>>(A, B, bias, C, M, N, K);
}

extern "C" void kernel_launch(void* const* d_in, const int* in_sizes, int n_in,
                              void* d_out, int out_size)
{
    const float* x      = (const float*)d_in[0];
    const int*   e_raw  = (const int*)d_in[1];
    const float* embW   = (const float*)d_in[2];
    const float* embB   = (const float*)d_in[3];
    const float* convW  = (const float*)d_in[4];
    const float* convB  = (const float*)d_in[5];
    const float* gamma  = (const float*)d_in[6];
    const float* beta   = (const float*)d_in[7];
    const float* W0 = (const float*)d_in[8];
    const float* b0 = (const float*)d_in[9];
    const float* W1 = (const float*)d_in[10];
    const float* b1 = (const float*)d_in[11];
    const float* W2 = (const float*)d_in[12];
    const float* b2 = (const float*)d_in[13];
    const float* W3 = (const float*)d_in[14];
    const float* b3 = (const float*)d_in[15];
    float* out = (float*)d_out;

    const int N = N_NODES;
    const int E = in_sizes[1] / 2;

    float *h, *hw, *dinv, *selfw, *c1, *c2, *c3, *csr_w;
    int *src32, *dst32, *cnt, *ptr, *fill, *csr_src, *bsum;
    cudaGetSymbolAddress((void**)&h,       g_h);
    cudaGetSymbolAddress((void**)&hw,      g_hw);
    cudaGetSymbolAddress((void**)&dinv,    g_dinv);
    cudaGetSymbolAddress((void**)&selfw,   g_self);
    cudaGetSymbolAddress((void**)&c1,      g_c1);
    cudaGetSymbolAddress((void**)&c2,      g_c2);
    cudaGetSymbolAddress((void**)&c3,      g_c3);
    cudaGetSymbolAddress((void**)&src32,   g_src32);
    cudaGetSymbolAddress((void**)&dst32,   g_dst32);
    cudaGetSymbolAddress((void**)&cnt,     g_cnt);
    cudaGetSymbolAddress((void**)&ptr,     g_ptr);
    cudaGetSymbolAddress((void**)&fill,    g_fill);
    cudaGetSymbolAddress((void**)&csr_src, g_csr_src);
    cudaGetSymbolAddress((void**)&csr_w,   g_csr_w);
    cudaGetSymbolAddress((void**)&bsum,    g_bsum);

    // 0. edge conversion + degree count
    detect_kernel<<<1, 256>>>(e_raw, 1024);
    convert_count_kernel<<<(E + 255) / 256, 256>>>(e_raw, src32, dst32, cnt, fill, E);
    norm_kernel<<<(N + 255) / 256, 256>>>(cnt, dinv, selfw, N);

    // 1. CSR build: exclusive scan + fill
    int nb = (N + SCAN_B - 1) / SCAN_B;
    scan1_kernel<<<nb, SCAN_B>>>(cnt, ptr, bsum, N);
    scan2_kernel<<<1, 256>>>(bsum, nb);
    scan3_kernel<<<nb + 1, SCAN_B>>>(ptr, bsum, N, E);
    csr_fill_kernel<<<(E + 255) / 256, 256>>>(src32, dst32, ptr, fill, dinv, csr_src, csr_w, E);

    // 2. embed: h = x @ embW + embB
    launch_gemm<false, true>(x, embW, embB, h, N, HID, 500);

    // 3. GCN layers: GEMM + fused aggregation/epilogue
    const int agg_blocks = (N + 7) / 8;
    for (int l = 0; l < 3; l++) {
        const float* Wl  = convW + (size_t)l * HID * HID;
        const float* cbl = convB + (size_t)l * HID;
        const float* gl  = gamma + (size_t)l * HID;
        const float* btl = beta  + (size_t)l * HID;

        launch_gemm<false, false>(h, Wl, nullptr, hw, N, HID, HID);
        agg_kernel<<<agg_blocks, 256>>>(ptr, csr_src, csr_w, selfw, hw, cbl, gl, btl, h, N);
    }

    // 4. classifier MLP
    launch_gemm<true,  true>(h,  W0, b0, c1,  N, 128, 256);
    launch_gemm<true,  true>(c1, W1, b1, c2,  N, 64,  128);
    launch_gemm<true,  true>(c2, W2, b2, c3,  N, 32,  64);
    launch_gemm<false, true>(c3, W3, b3, out, N, 40,  32);
}

// round 5
// speedup vs baseline: 3.2269x; 2.4933x over previous
#include <cuda_runtime.h>
#include <stdint.h>

#define N_NODES 100000
#define N_EDGES 1600000
#define HID 256
#define SCAN_B 1024

// ---------------- scratch (device globals; no allocation allowed) ----------
__device__ float g_h[(size_t)N_NODES * HID];
__device__ float g_hw[(size_t)N_NODES * HID];
__device__ float g_dinv[N_NODES];
__device__ float g_self[N_NODES];
__device__ float g_c1[(size_t)N_NODES * 128];
__device__ float g_c2[(size_t)N_NODES * 64];
__device__ float g_c3[(size_t)N_NODES * 32];
__device__ int   g_src32[N_EDGES];
__device__ int   g_dst32[N_EDGES];
__device__ int   g_cnt[N_NODES];
__device__ int   g_ptr[N_NODES + 1];
__device__ int   g_fill[N_NODES];
__device__ int   g_csr_src[N_EDGES];
__device__ float g_csr_w[N_EDGES];
__device__ int   g_bsum[(N_NODES + SCAN_B - 1) / SCAN_B + 1];
__device__ int   g_is64;

__device__ __forceinline__ uint32_t f2tf32(float f) {
    uint32_t o;
    asm("cvt.rna.tf32.f32 %0, %1;" : "=r"(o) : "f"(f));
    return o;
}

// =================== tf32 mma.sync GEMM (sm_80+ portable) ===================
// C[M,N] = A[M,K] @ W[K,N] (+bias)(ReLU).  CTA tile 128x128, BK=32.
// 8 warps: 2 (M) x 4 (N); warp tile 64x32 = 4x4 m16n8k8 tiles.
template<bool BIAS, bool RELU>
__global__ __launch_bounds__(256, 2) void mma_gemm_kernel(
    const float* __restrict__ A, const float* __restrict__ W,
    const float* __restrict__ bias, float* __restrict__ C,
    int M, int N, int K)
{
    __shared__ uint32_t As[128][36];   // [m][k], pad 4 -> banks 4m+k
    __shared__ uint32_t Bs[32][136];   // [k][n], pad 8 -> banks 8k+n

    const int tid    = threadIdx.x;
    const int wid    = tid >> 5;
    const int lane   = tid & 31;
    const int gid    = lane >> 2;     // group id (0..7)
    const int t4     = lane & 3;      // thread in group (0..3)
    const int warp_m = wid >> 2;      // 0..1
    const int warp_n = wid & 3;       // 0..3
    const int row0   = blockIdx.y * 128;
    const int col0   = blockIdx.x * 128;

    float acc[4][4][4];
#pragma unroll
    for (int mt = 0; mt < 4; mt++)
#pragma unroll
        for (int nt = 0; nt < 4; nt++)
#pragma unroll
            for (int q = 0; q < 4; q++) acc[mt][nt][q] = 0.0f;

    for (int k0 = 0; k0 < K; k0 += 32) {
        // load A tile: 128 x 32, float4 per thread x4
#pragma unroll
        for (int t = 0; t < 4; t++) {
            int i  = tid + t * 256;          // 0..1023
            int r  = i >> 3;
            int c4 = (i & 7) * 4;
            int gr = row0 + r, gk = k0 + c4;
            uint4 v = make_uint4(0u, 0u, 0u, 0u);
            if (gr < M && gk + 4 <= K) {
                float4 f = *reinterpret_cast<const float4*>(A + (size_t)gr * K + gk);
                v.x = f2tf32(f.x); v.y = f2tf32(f.y); v.z = f2tf32(f.z); v.w = f2tf32(f.w);
            }
            *reinterpret_cast<uint4*>(&As[r][c4]) = v;
        }
        // load B tile: 32 x 128
#pragma unroll
        for (int t = 0; t < 4; t++) {
            int i  = tid + t * 256;
            int k  = i >> 5;                 // 0..31
            int n4 = (i & 31) * 4;
            int gk = k0 + k;
            uint4 v = make_uint4(0u, 0u, 0u, 0u);
            if (gk < K) {
                float4 f = *reinterpret_cast<const float4*>(W + (size_t)gk * N + col0 + n4);
                v.x = f2tf32(f.x); v.y = f2tf32(f.y); v.z = f2tf32(f.z); v.w = f2tf32(f.w);
            }
            *reinterpret_cast<uint4*>(&Bs[k][n4]) = v;
        }
        __syncthreads();

#pragma unroll
        for (int ks = 0; ks < 4; ks++) {
            const int kb = ks * 8;
            uint32_t a[4][4], b[4][2];
#pragma unroll
            for (int mt = 0; mt < 4; mt++) {
                int r = warp_m * 64 + mt * 16 + gid;
                a[mt][0] = As[r][kb + t4];
                a[mt][1] = As[r + 8][kb + t4];
                a[mt][2] = As[r][kb + t4 + 4];
                a[mt][3] = As[r + 8][kb + t4 + 4];
            }
#pragma unroll
            for (int nt = 0; nt < 4; nt++) {
                int c = warp_n * 32 + nt * 8 + gid;
                b[nt][0] = Bs[kb + t4][c];
                b[nt][1] = Bs[kb + t4 + 4][c];
            }
#pragma unroll
            for (int mt = 0; mt < 4; mt++)
#pragma unroll
                for (int nt = 0; nt < 4; nt++) {
                    asm volatile(
                        "mma.sync.aligned.m16n8k8.row.col.f32.tf32.tf32.f32 "
                        "{%0,%1,%2,%3}, {%4,%5,%6,%7}, {%8,%9}, {%0,%1,%2,%3};"
                        : "+f"(acc[mt][nt][0]), "+f"(acc[mt][nt][1]),
                          "+f"(acc[mt][nt][2]), "+f"(acc[mt][nt][3])
                        : "r"(a[mt][0]), "r"(a[mt][1]), "r"(a[mt][2]), "r"(a[mt][3]),
                          "r"(b[nt][0]), "r"(b[nt][1]));
                }
        }
        __syncthreads();
    }

    // epilogue: each thread owns (rows gid, gid+8) x cols (2*t4, 2*t4+1) per tile
#pragma unroll
    for (int mt = 0; mt < 4; mt++) {
#pragma unroll
        for (int half = 0; half < 2; half++) {
            int gr = row0 + warp_m * 64 + mt * 16 + gid + half * 8;
            if (gr >= M) continue;
#pragma unroll
            for (int nt = 0; nt < 4; nt++) {
                int gc = col0 + warp_n * 32 + nt * 8 + t4 * 2;
                float2 o;
                o.x = acc[mt][nt][half * 2 + 0];
                o.y = acc[mt][nt][half * 2 + 1];
                if (BIAS) {
                    o.x += __ldg(&bias[gc]);
                    o.y += __ldg(&bias[gc + 1]);
                }
                if (RELU) {
                    o.x = fmaxf(o.x, 0.0f);
                    o.y = fmaxf(o.y, 0.0f);
                }
                *reinterpret_cast<float2*>(C + (size_t)gr * N + gc) = o;
            }
        }
    }
}

// ---------------- edge dtype detection + conversion -------------------------
__global__ void detect_kernel(const int* __restrict__ e_raw, int n_check) {
    __shared__ int nz;
    if (threadIdx.x == 0) nz = 0;
    __syncthreads();
    for (int i = threadIdx.x; i < n_check; i += blockDim.x)
        if (e_raw[2 * i + 1] != 0) atomicAdd(&nz, 1);
    __syncthreads();
    if (threadIdx.x == 0) g_is64 = (nz == 0) ? 1 : 0;
}

__global__ void convert_count_kernel(const int* __restrict__ e_raw,
                                     int* __restrict__ src32, int* __restrict__ dst32,
                                     int* __restrict__ cnt, int* __restrict__ fill, int E) {
    int i = blockIdx.x * blockDim.x + threadIdx.x;
    if (i < N_NODES) { cnt[i] = 0; fill[i] = 0; }
    if (i >= E) return;
    int s, d;
    if (g_is64) { s = e_raw[2 * i]; d = e_raw[2 * (E + i)]; }
    else        { s = e_raw[i];     d = e_raw[E + i]; }
    src32[i] = s;
    dst32[i] = d;
    atomicAdd(&cnt[d], 1);
}

__global__ void norm_kernel(const int* __restrict__ cnt,
                            float* __restrict__ dinv, float* __restrict__ selfw, int n) {
    int i = blockIdx.x * blockDim.x + threadIdx.x;
    if (i < n) {
        float d = (float)cnt[i] + 1.0f;
        dinv[i]  = rsqrtf(d);
        selfw[i] = 1.0f / d;
    }
}

// ---------------- exclusive scan of cnt -> ptr ------------------------------
__global__ void scan1_kernel(const int* __restrict__ cnt, int* __restrict__ ptr,
                             int* __restrict__ bsum, int n) {
    __shared__ int sh[SCAN_B];
    int b = blockIdx.x;
    int i = b * SCAN_B + threadIdx.x;
    int v = (i < n) ? cnt[i] : 0;
    sh[threadIdx.x] = v;
    __syncthreads();
    for (int off = 1; off < SCAN_B; off <<= 1) {
        int t = (threadIdx.x >= off) ? sh[threadIdx.x - off] : 0;
        __syncthreads();
        sh[threadIdx.x] += t;
        __syncthreads();
    }
    if (i < n) ptr[i] = sh[threadIdx.x] - v;
    if (threadIdx.x == SCAN_B - 1) bsum[b] = sh[SCAN_B - 1];
}

__global__ void scan2_kernel(int* __restrict__ bsum, int nb) {
    __shared__ int sh[256];
    int v = (threadIdx.x < nb) ? bsum[threadIdx.x] : 0;
    sh[threadIdx.x] = v;
    __syncthreads();
    for (int off = 1; off < 256; off <<= 1) {
        int t = (threadIdx.x >= off) ? sh[threadIdx.x - off] : 0;
        __syncthreads();
        sh[threadIdx.x] += t;
        __syncthreads();
    }
    if (threadIdx.x < nb) bsum[threadIdx.x] = sh[threadIdx.x] - v;
}

__global__ void scan3_kernel(int* __restrict__ ptr, const int* __restrict__ bsum,
                             int n, int E) {
    int i = blockIdx.x * SCAN_B + threadIdx.x;
    if (i < n) ptr[i] += bsum[blockIdx.x];
    if (i == n) ptr[n] = E;
}

__global__ void csr_fill_kernel(const int* __restrict__ src, const int* __restrict__ dst,
                                const int* __restrict__ ptr, int* __restrict__ fill,
                                const float* __restrict__ dinv,
                                int* __restrict__ csr_src, float* __restrict__ csr_w, int E) {
    int i = blockIdx.x * blockDim.x + threadIdx.x;
    if (i >= E) return;
    int s = src[i], d = dst[i];
    int pos = atomicAdd(&fill[d], 1);
    int idx = ptr[d] + pos;
    csr_src[idx] = s;
    csr_w[idx] = dinv[s] * dinv[d];
}

// ---------------- SIMT GEMM (small classifier tail) --------------------------
template<int BM, int BN, int BK, int TM, int TN, bool RELU, bool BIAS>
__global__ void gemm_kernel(const float* __restrict__ A, const float* __restrict__ B,
                            const float* __restrict__ bias, float* __restrict__ C,
                            int M, int N, int K)
{
    constexpr int THREADS = (BM / TM) * (BN / TN);
    __shared__ float As[BK][BM];
    __shared__ float Bs[BK][BN];

    const int tid = threadIdx.x;
    const int tx  = tid % (BN / TN);
    const int ty  = tid / (BN / TN);
    const int row0 = blockIdx.y * BM;
    const int col0 = blockIdx.x * BN;

    float acc[TM][TN];
#pragma unroll
    for (int i = 0; i < TM; i++)
#pragma unroll
        for (int j = 0; j < TN; j++) acc[i][j] = 0.0f;

    for (int k0 = 0; k0 < K; k0 += BK) {
#pragma unroll 4
        for (int i = tid; i < BM * BK; i += THREADS) {
            int r = i / BK, c = i % BK;
            int gr = row0 + r, gc = k0 + c;
            As[c][r] = (gr < M && gc < K) ? A[(size_t)gr * K + gc] : 0.0f;
        }
#pragma unroll 4
        for (int i = tid; i < BK * BN; i += THREADS) {
            int r = i / BN, c = i % BN;
            int gk = k0 + r, gc = col0 + c;
            Bs[r][c] = (gk < K && gc < N) ? B[(size_t)gk * N + gc] : 0.0f;
        }
        __syncthreads();
#pragma unroll
        for (int kk = 0; kk < BK; kk++) {
            float a[TM], b[TN];
#pragma unroll
            for (int i = 0; i < TM; i++) a[i] = As[kk][ty * TM + i];
#pragma unroll
            for (int j = 0; j < TN; j++) b[j] = Bs[kk][tx * TN + j];
#pragma unroll
            for (int i = 0; i < TM; i++)
#pragma unroll
                for (int j = 0; j < TN; j++)
                    acc[i][j] = fmaf(a[i], b[j], acc[i][j]);
        }
        __syncthreads();
    }

#pragma unroll
    for (int i = 0; i < TM; i++) {
        int gr = row0 + ty * TM + i;
        if (gr >= M) continue;
#pragma unroll
        for (int j = 0; j < TN; j++) {
            int gc = col0 + tx * TN + j;
            if (gc >= N) continue;
            float v = acc[i][j];
            if (BIAS) v += bias[gc];
            if (RELU) v = fmaxf(v, 0.0f);
            C[(size_t)gr * N + gc] = v;
        }
    }
}

// ---------------- fused aggregation + BN + ReLU + residual ------------------
__global__ void agg_kernel(const int* __restrict__ ptr,
                           const int* __restrict__ csr_src,
                           const float* __restrict__ csr_w,
                           const float* __restrict__ selfw,
                           const float* __restrict__ hw,
                           const float* __restrict__ cb,
                           const float* __restrict__ gamma,
                           const float* __restrict__ beta,
                           float* __restrict__ h, int N)
{
    int d = blockIdx.x * 8 + (threadIdx.x >> 5);
    if (d >= N) return;
    int lane = threadIdx.x & 31;

    float4 a0 = make_float4(0.f, 0.f, 0.f, 0.f);
    float4 a1 = make_float4(0.f, 0.f, 0.f, 0.f);

    int beg = __ldg(&ptr[d]);
    int end = __ldg(&ptr[d + 1]);
#pragma unroll 2
    for (int j = beg; j < end; j++) {
        int s = __ldg(&csr_src[j]);
        float w = __ldg(&csr_w[j]);
        const float4* srow = reinterpret_cast<const float4*>(hw + (size_t)s * HID);
        float4 v0 = __ldg(&srow[lane]);
        float4 v1 = __ldg(&srow[lane + 32]);
        a0.x = fmaf(v0.x, w, a0.x); a0.y = fmaf(v0.y, w, a0.y);
        a0.z = fmaf(v0.z, w, a0.z); a0.w = fmaf(v0.w, w, a0.w);
        a1.x = fmaf(v1.x, w, a1.x); a1.y = fmaf(v1.y, w, a1.y);
        a1.z = fmaf(v1.z, w, a1.z); a1.w = fmaf(v1.w, w, a1.w);
    }

    float sw = __ldg(&selfw[d]);
    const float4* drow = reinterpret_cast<const float4*>(hw + (size_t)d * HID);
    float4 s0 = __ldg(&drow[lane]);
    float4 s1 = __ldg(&drow[lane + 32]);
    a0.x = fmaf(s0.x, sw, a0.x); a0.y = fmaf(s0.y, sw, a0.y);
    a0.z = fmaf(s0.z, sw, a0.z); a0.w = fmaf(s0.w, sw, a0.w);
    a1.x = fmaf(s1.x, sw, a1.x); a1.y = fmaf(s1.y, sw, a1.y);
    a1.z = fmaf(s1.z, sw, a1.z); a1.w = fmaf(s1.w, sw, a1.w);

    const float4* cb4 = reinterpret_cast<const float4*>(cb);
    const float4* g4  = reinterpret_cast<const float4*>(gamma);
    const float4* bt4 = reinterpret_cast<const float4*>(beta);
    float4* hrow = reinterpret_cast<float4*>(h + (size_t)d * HID);

#pragma unroll
    for (int half = 0; half < 2; half++) {
        int c = lane + 32 * half;
        float4 a  = half ? a1 : a0;
        float4 b  = __ldg(&cb4[c]);
        float4 g  = __ldg(&g4[c]);
        float4 bt = __ldg(&bt4[c]);
        float4 hv = hrow[c];
        hv.x += fmaxf(fmaf(a.x + b.x, g.x, bt.x), 0.0f);
        hv.y += fmaxf(fmaf(a.y + b.y, g.y, bt.y), 0.0f);
        hv.z += fmaxf(fmaf(a.z + b.z, g.z, bt.z), 0.0f);
        hv.w += fmaxf(fmaf(a.w + b.w, g.w, bt.w), 0.0f);
        hrow[c] = hv;
    }
}

// ---------------- host launcher ---------------------------------------------
static inline dim3 gemm_grid(int M, int N) {
    return dim3((N + 63) / 64, (M + 127) / 128);
}

template<bool RELU, bool BIAS>
static void launch_gemm(const float* A, const float* B, const float* bias, float* C,
                        int M, int N, int K) {
    gemm_kernel<128, 64, 16, 8, 4, RELU, BIAS><<<gemm_grid(M, N), 256>>>(A, B, bias, C, M, N, K);
}

template<bool BIAS, bool RELU>
static void launch_mma_gemm(const float* A, const float* W, const float* bias, float* C,
                            int M, int N, int K) {
    dim3 grid(N / 128, (M + 127) / 128);
    mma_gemm_kernel<BIAS, RELU><<<grid, 256>>>(A, W, bias, C, M, N, K);
}

extern "C" void kernel_launch(void* const* d_in, const int* in_sizes, int n_in,
                              void* d_out, int out_size)
{
    const float* x      = (const float*)d_in[0];
    const int*   e_raw  = (const int*)d_in[1];
    const float* embW   = (const float*)d_in[2];
    const float* embB   = (const float*)d_in[3];
    const float* convW  = (const float*)d_in[4];
    const float* convB  = (const float*)d_in[5];
    const float* gamma  = (const float*)d_in[6];
    const float* beta   = (const float*)d_in[7];
    const float* W0 = (const float*)d_in[8];
    const float* b0 = (const float*)d_in[9];
    const float* W1 = (const float*)d_in[10];
    const float* b1 = (const float*)d_in[11];
    const float* W2 = (const float*)d_in[12];
    const float* b2 = (const float*)d_in[13];
    const float* W3 = (const float*)d_in[14];
    const float* b3 = (const float*)d_in[15];
    float* out = (float*)d_out;

    const int N = N_NODES;
    const int E = in_sizes[1] / 2;

    float *h, *hw, *dinv, *selfw, *c1, *c2, *c3, *csr_w;
    int *src32, *dst32, *cnt, *ptr, *fill, *csr_src, *bsum;
    cudaGetSymbolAddress((void**)&h,       g_h);
    cudaGetSymbolAddress((void**)&hw,      g_hw);
    cudaGetSymbolAddress((void**)&dinv,    g_dinv);
    cudaGetSymbolAddress((void**)&selfw,   g_self);
    cudaGetSymbolAddress((void**)&c1,      g_c1);
    cudaGetSymbolAddress((void**)&c2,      g_c2);
    cudaGetSymbolAddress((void**)&c3,      g_c3);
    cudaGetSymbolAddress((void**)&src32,   g_src32);
    cudaGetSymbolAddress((void**)&dst32,   g_dst32);
    cudaGetSymbolAddress((void**)&cnt,     g_cnt);
    cudaGetSymbolAddress((void**)&ptr,     g_ptr);
    cudaGetSymbolAddress((void**)&fill,    g_fill);
    cudaGetSymbolAddress((void**)&csr_src, g_csr_src);
    cudaGetSymbolAddress((void**)&csr_w,   g_csr_w);
    cudaGetSymbolAddress((void**)&bsum,    g_bsum);

    // 0. edge conversion + degree count
    detect_kernel<<<1, 256>>>(e_raw, 1024);
    convert_count_kernel<<<(E + 255) / 256, 256>>>(e_raw, src32, dst32, cnt, fill, E);
    norm_kernel<<<(N + 255) / 256, 256>>>(cnt, dinv, selfw, N);

    // 1. CSR build
    int nb = (N + SCAN_B - 1) / SCAN_B;
    scan1_kernel<<<nb, SCAN_B>>>(cnt, ptr, bsum, N);
    scan2_kernel<<<1, 256>>>(bsum, nb);
    scan3_kernel<<<nb + 1, SCAN_B>>>(ptr, bsum, N, E);
    csr_fill_kernel<<<(E + 255) / 256, 256>>>(src32, dst32, ptr, fill, dinv, csr_src, csr_w, E);

    // 2. embed: h = x @ embW + embB  (tf32 tensor)
    launch_mma_gemm<true, false>(x, embW, embB, h, N, HID, 500);

    // 3. GCN layers: tf32 tensor GEMM + fused aggregation/epilogue
    const int agg_blocks = (N + 7) / 8;
    for (int l = 0; l < 3; l++) {
        const float* Wl  = convW + (size_t)l * HID * HID;
        const float* cbl = convB + (size_t)l * HID;
        const float* gl  = gamma + (size_t)l * HID;
        const float* btl = beta  + (size_t)l * HID;

        launch_mma_gemm<false, false>(h, Wl, nullptr, hw, N, HID, HID);
        agg_kernel<<<agg_blocks, 256>>>(ptr, csr_src, csr_w, selfw, hw, cbl, gl, btl, h, N);
    }

    // 4. classifier MLP: first layer tensor, small tail SIMT
    launch_mma_gemm<true, true>(h, W0, b0, c1, N, 128, 256);
    launch_gemm<true,  true>(c1, W1, b1, c2,  N, 64,  128);
    launch_gemm<true,  true>(c2, W2, b2, c3,  N, 32,  64);
    launch_gemm<false, true>(c3, W3, b3, out, N, 40,  32);
}

// round 6
// speedup vs baseline: 3.3440x; 1.0363x over previous
#include <cuda_runtime.h>
#include <stdint.h>

#define N_NODES 100000
#define N_EDGES 1600000
#define HID 256
#define SCAN_B 1024

// ---------------- scratch (device globals; no allocation allowed) ----------
__device__ float g_h[(size_t)N_NODES * HID];
__device__ float g_hw[(size_t)N_NODES * HID];
__device__ float g_dinv[N_NODES];
__device__ float g_self[N_NODES];
__device__ float g_c1[(size_t)N_NODES * 128];
__device__ float g_c2[(size_t)N_NODES * 64];
__device__ float g_c3[(size_t)N_NODES * 32];
__device__ int   g_src32[N_EDGES];
__device__ int   g_dst32[N_EDGES];
__device__ int   g_cnt[N_NODES];
__device__ int   g_ptr[N_NODES + 1];
__device__ int   g_fill[N_NODES];
__device__ int   g_csr_src[N_EDGES];
__device__ float g_csr_w[N_EDGES];
__device__ int   g_bsum[(N_NODES + SCAN_B - 1) / SCAN_B + 1];
__device__ int   g_is64;

__device__ __forceinline__ uint32_t f2tf32(float f) {
    uint32_t o;
    asm("cvt.rna.tf32.f32 %0, %1;" : "=r"(o) : "f"(f));
    return o;
}
__device__ __forceinline__ uint32_t smem_u32(const void* p) {
    uint32_t a;
    asm("{ .reg .u64 t; cvta.to.shared.u64 t, %1; cvt.u32.u64 %0, t; }" : "=r"(a) : "l"(p));
    return a;
}
__device__ __forceinline__ void cp16(uint32_t dst, const void* src, int valid_bytes) {
    asm volatile("cp.async.ca.shared.global [%0], [%1], 16, %2;"
                 :: "r"(dst), "l"(src), "r"(valid_bytes) : "memory");
}
#define CP_COMMIT() asm volatile("cp.async.commit_group;" ::: "memory")
#define CP_WAIT(n)  asm volatile("cp.async.wait_group %0;" :: "n"(n) : "memory")

// =================== tf32 mma.sync GEMM, cp.async 2-stage pipeline ==========
// C[M,N] = A[M,K] @ W[K,N] (+bias)(ReLU).  CTA tile 128x128, BK=32.
// 8 warps: 2 (M) x 4 (N); warp tile 64x32 = 4x4 m16n8k8 tiles.
// Dynamic smem: 2 stages x (A 128x36 fp32 + B 32x136 fp32) = 71680 B.
#define ASTR 36
#define BSTR 136
#define ASZ  (128 * ASTR)
#define BSZ  (32 * BSTR)
#define STG  (ASZ + BSZ)
#define MMA_SMEM (2 * STG * 4)

template<bool BIAS, bool RELU>
__global__ void __launch_bounds__(256) mma_gemm_kernel(
    const float* __restrict__ A, const float* __restrict__ W,
    const float* __restrict__ bias, float* __restrict__ C,
    int M, int N, int K)
{
    extern __shared__ float sm[];
    const uint32_t sbase = smem_u32(sm);

    const int tid    = threadIdx.x;
    const int wid    = tid >> 5;
    const int lane   = tid & 31;
    const int gid    = lane >> 2;
    const int t4     = lane & 3;
    const int warp_m = wid >> 2;
    const int warp_n = wid & 3;
    const int row0   = blockIdx.y * 128;
    const int col0   = blockIdx.x * 128;

    float acc[4][4][4];
#pragma unroll
    for (int mt = 0; mt < 4; mt++)
#pragma unroll
        for (int nt = 0; nt < 4; nt++)
#pragma unroll
            for (int q = 0; q < 4; q++) acc[mt][nt][q] = 0.0f;

    const int n_chunks = (K + 31) / 32;

    // async tile loader for chunk ch into stage st
    auto load_chunk = [&](int ch, int st) {
        const int k0 = ch * 32;
        const uint32_t s0 = sbase + (uint32_t)(st * STG) * 4u;
#pragma unroll
        for (int t = 0; t < 4; t++) {
            int i  = tid + t * 256;
            int r  = i >> 3;
            int c4 = (i & 7) * 4;
            int gr = row0 + r, gk = k0 + c4;
            int valid = 0;
            if (gr < M) {
                int rem = (K - gk) * 4;
                valid = rem > 16 ? 16 : (rem > 0 ? rem : 0);
            }
            const float* p = valid ? (A + (size_t)gr * K + gk) : A;
            cp16(s0 + (uint32_t)(r * ASTR + c4) * 4u, p, valid);
        }
#pragma unroll
        for (int t = 0; t < 4; t++) {
            int i  = tid + t * 256;
            int k  = i >> 5;
            int n4 = (i & 31) * 4;
            int gk = k0 + k, gn = col0 + n4;
            int valid = (gk < K && gn < N) ? 16 : 0;
            const float* p = valid ? (W + (size_t)gk * N + gn) : W;
            cp16(s0 + (uint32_t)(ASZ + k * BSTR + n4) * 4u, p, valid);
        }
        CP_COMMIT();
    };

    load_chunk(0, 0);

    for (int ch = 0; ch < n_chunks; ch++) {
        if (ch + 1 < n_chunks) {
            load_chunk(ch + 1, (ch + 1) & 1);
            CP_WAIT(1);
        } else {
            CP_WAIT(0);
        }
        __syncthreads();

        const float* As = sm + (ch & 1) * STG;
        const float* Bs = As + ASZ;
#pragma unroll
        for (int ks = 0; ks < 4; ks++) {
            const int kb = ks * 8;
            uint32_t a[4][4], b[4][2];
#pragma unroll
            for (int mt = 0; mt < 4; mt++) {
                int r = warp_m * 64 + mt * 16 + gid;
                a[mt][0] = f2tf32(As[r * ASTR + kb + t4]);
                a[mt][1] = f2tf32(As[(r + 8) * ASTR + kb + t4]);
                a[mt][2] = f2tf32(As[r * ASTR + kb + t4 + 4]);
                a[mt][3] = f2tf32(As[(r + 8) * ASTR + kb + t4 + 4]);
            }
#pragma unroll
            for (int nt = 0; nt < 4; nt++) {
                int c = warp_n * 32 + nt * 8 + gid;
                b[nt][0] = f2tf32(Bs[(kb + t4) * BSTR + c]);
                b[nt][1] = f2tf32(Bs[(kb + t4 + 4) * BSTR + c]);
            }
#pragma unroll
            for (int mt = 0; mt < 4; mt++)
#pragma unroll
                for (int nt = 0; nt < 4; nt++) {
                    asm volatile(
                        "mma.sync.aligned.m16n8k8.row.col.f32.tf32.tf32.f32 "
                        "{%0,%1,%2,%3}, {%4,%5,%6,%7}, {%8,%9}, {%0,%1,%2,%3};"
                        : "+f"(acc[mt][nt][0]), "+f"(acc[mt][nt][1]),
                          "+f"(acc[mt][nt][2]), "+f"(acc[mt][nt][3])
                        : "r"(a[mt][0]), "r"(a[mt][1]), "r"(a[mt][2]), "r"(a[mt][3]),
                          "r"(b[nt][0]), "r"(b[nt][1]));
                }
        }
        __syncthreads();
    }

    // epilogue
#pragma unroll
    for (int mt = 0; mt < 4; mt++) {
#pragma unroll
        for (int half = 0; half < 2; half++) {
            int gr = row0 + warp_m * 64 + mt * 16 + gid + half * 8;
            if (gr >= M) continue;
#pragma unroll
            for (int nt = 0; nt < 4; nt++) {
                int gc = col0 + warp_n * 32 + nt * 8 + t4 * 2;
                if (gc >= N) continue;
                float2 o;
                o.x = acc[mt][nt][half * 2 + 0];
                o.y = acc[mt][nt][half * 2 + 1];
                if (BIAS) {
                    o.x += __ldg(&bias[gc]);
                    o.y += __ldg(&bias[gc + 1]);
                }
                if (RELU) {
                    o.x = fmaxf(o.x, 0.0f);
                    o.y = fmaxf(o.y, 0.0f);
                }
                *reinterpret_cast<float2*>(C + (size_t)gr * N + gc) = o;
            }
        }
    }
}

// ---------------- edge dtype detection + conversion -------------------------
__global__ void detect_kernel(const int* __restrict__ e_raw, int n_check) {
    __shared__ int nz;
    if (threadIdx.x == 0) nz = 0;
    __syncthreads();
    for (int i = threadIdx.x; i < n_check; i += blockDim.x)
        if (e_raw[2 * i + 1] != 0) atomicAdd(&nz, 1);
    __syncthreads();
    if (threadIdx.x == 0) g_is64 = (nz == 0) ? 1 : 0;
}

__global__ void convert_count_kernel(const int* __restrict__ e_raw,
                                     int* __restrict__ src32, int* __restrict__ dst32,
                                     int* __restrict__ cnt, int* __restrict__ fill, int E) {
    int i = blockIdx.x * blockDim.x + threadIdx.x;
    if (i < N_NODES) { cnt[i] = 0; fill[i] = 0; }
    if (i >= E) return;
    int s, d;
    if (g_is64) { s = e_raw[2 * i]; d = e_raw[2 * (E + i)]; }
    else        { s = e_raw[i];     d = e_raw[E + i]; }
    src32[i] = s;
    dst32[i] = d;
    atomicAdd(&cnt[d], 1);
}

__global__ void norm_kernel(const int* __restrict__ cnt,
                            float* __restrict__ dinv, float* __restrict__ selfw, int n) {
    int i = blockIdx.x * blockDim.x + threadIdx.x;
    if (i < n) {
        float d = (float)cnt[i] + 1.0f;
        dinv[i]  = rsqrtf(d);
        selfw[i] = 1.0f / d;
    }
}

// ---------------- exclusive scan of cnt -> ptr ------------------------------
__global__ void scan1_kernel(const int* __restrict__ cnt, int* __restrict__ ptr,
                             int* __restrict__ bsum, int n) {
    __shared__ int sh[SCAN_B];
    int b = blockIdx.x;
    int i = b * SCAN_B + threadIdx.x;
    int v = (i < n) ? cnt[i] : 0;
    sh[threadIdx.x] = v;
    __syncthreads();
    for (int off = 1; off < SCAN_B; off <<= 1) {
        int t = (threadIdx.x >= off) ? sh[threadIdx.x - off] : 0;
        __syncthreads();
        sh[threadIdx.x] += t;
        __syncthreads();
    }
    if (i < n) ptr[i] = sh[threadIdx.x] - v;
    if (threadIdx.x == SCAN_B - 1) bsum[b] = sh[SCAN_B - 1];
}

__global__ void scan2_kernel(int* __restrict__ bsum, int nb) {
    __shared__ int sh[256];
    int v = (threadIdx.x < nb) ? bsum[threadIdx.x] : 0;
    sh[threadIdx.x] = v;
    __syncthreads();
    for (int off = 1; off < 256; off <<= 1) {
        int t = (threadIdx.x >= off) ? sh[threadIdx.x - off] : 0;
        __syncthreads();
        sh[threadIdx.x] += t;
        __syncthreads();
    }
    if (threadIdx.x < nb) bsum[threadIdx.x] = sh[threadIdx.x] - v;
}

__global__ void scan3_kernel(int* __restrict__ ptr, const int* __restrict__ bsum,
                             int n, int E) {
    int i = blockIdx.x * SCAN_B + threadIdx.x;
    if (i < n) ptr[i] += bsum[blockIdx.x];
    if (i == n) ptr[n] = E;
}

__global__ void csr_fill_kernel(const int* __restrict__ src, const int* __restrict__ dst,
                                const int* __restrict__ ptr, int* __restrict__ fill,
                                const float* __restrict__ dinv,
                                int* __restrict__ csr_src, float* __restrict__ csr_w, int E) {
    int i = blockIdx.x * blockDim.x + threadIdx.x;
    if (i >= E) return;
    int s = src[i], d = dst[i];
    int pos = atomicAdd(&fill[d], 1);
    int idx = ptr[d] + pos;
    csr_src[idx] = s;
    csr_w[idx] = dinv[s] * dinv[d];
}

// ---------------- SIMT GEMM (small classifier tail) --------------------------
template<int BM, int BN, int BK, int TM, int TN, bool RELU, bool BIAS>
__global__ void gemm_kernel(const float* __restrict__ A, const float* __restrict__ B,
                            const float* __restrict__ bias, float* __restrict__ C,
                            int M, int N, int K)
{
    constexpr int THREADS = (BM / TM) * (BN / TN);
    __shared__ float As[BK][BM];
    __shared__ float Bs[BK][BN];

    const int tid = threadIdx.x;
    const int tx  = tid % (BN / TN);
    const int ty  = tid / (BN / TN);
    const int row0 = blockIdx.y * BM;
    const int col0 = blockIdx.x * BN;

    float acc[TM][TN];
#pragma unroll
    for (int i = 0; i < TM; i++)
#pragma unroll
        for (int j = 0; j < TN; j++) acc[i][j] = 0.0f;

    for (int k0 = 0; k0 < K; k0 += BK) {
#pragma unroll 4
        for (int i = tid; i < BM * BK; i += THREADS) {
            int r = i / BK, c = i % BK;
            int gr = row0 + r, gc = k0 + c;
            As[c][r] = (gr < M && gc < K) ? A[(size_t)gr * K + gc] : 0.0f;
        }
#pragma unroll 4
        for (int i = tid; i < BK * BN; i += THREADS) {
            int r = i / BN, c = i % BN;
            int gk = k0 + r, gc = col0 + c;
            Bs[r][c] = (gk < K && gc < N) ? B[(size_t)gk * N + gc] : 0.0f;
        }
        __syncthreads();
#pragma unroll
        for (int kk = 0; kk < BK; kk++) {
            float a[TM], b[TN];
#pragma unroll
            for (int i = 0; i < TM; i++) a[i] = As[kk][ty * TM + i];
#pragma unroll
            for (int j = 0; j < TN; j++) b[j] = Bs[kk][tx * TN + j];
#pragma unroll
            for (int i = 0; i < TM; i++)
#pragma unroll
                for (int j = 0; j < TN; j++)
                    acc[i][j] = fmaf(a[i], b[j], acc[i][j]);
        }
        __syncthreads();
    }

#pragma unroll
    for (int i = 0; i < TM; i++) {
        int gr = row0 + ty * TM + i;
        if (gr >= M) continue;
#pragma unroll
        for (int j = 0; j < TN; j++) {
            int gc = col0 + tx * TN + j;
            if (gc >= N) continue;
            float v = acc[i][j];
            if (BIAS) v += bias[gc];
            if (RELU) v = fmaxf(v, 0.0f);
            C[(size_t)gr * N + gc] = v;
        }
    }
}

// ---------------- fused aggregation + BN + ReLU + residual ------------------
__global__ void agg_kernel(const int* __restrict__ ptr,
                           const int* __restrict__ csr_src,
                           const float* __restrict__ csr_w,
                           const float* __restrict__ selfw,
                           const float* __restrict__ hw,
                           const float* __restrict__ cb,
                           const float* __restrict__ gamma,
                           const float* __restrict__ beta,
                           float* __restrict__ h, int N)
{
    int d = blockIdx.x * 8 + (threadIdx.x >> 5);
    if (d >= N) return;
    int lane = threadIdx.x & 31;

    float4 a0 = make_float4(0.f, 0.f, 0.f, 0.f);
    float4 a1 = make_float4(0.f, 0.f, 0.f, 0.f);

    int beg = __ldg(&ptr[d]);
    int end = __ldg(&ptr[d + 1]);
#pragma unroll 2
    for (int j = beg; j < end; j++) {
        int s = __ldg(&csr_src[j]);
        float w = __ldg(&csr_w[j]);
        const float4* srow = reinterpret_cast<const float4*>(hw + (size_t)s * HID);
        float4 v0 = __ldg(&srow[lane]);
        float4 v1 = __ldg(&srow[lane + 32]);
        a0.x = fmaf(v0.x, w, a0.x); a0.y = fmaf(v0.y, w, a0.y);
        a0.z = fmaf(v0.z, w, a0.z); a0.w = fmaf(v0.w, w, a0.w);
        a1.x = fmaf(v1.x, w, a1.x); a1.y = fmaf(v1.y, w, a1.y);
        a1.z = fmaf(v1.z, w, a1.z); a1.w = fmaf(v1.w, w, a1.w);
    }

    float sw = __ldg(&selfw[d]);
    const float4* drow = reinterpret_cast<const float4*>(hw + (size_t)d * HID);
    float4 s0 = __ldg(&drow[lane]);
    float4 s1 = __ldg(&drow[lane + 32]);
    a0.x = fmaf(s0.x, sw, a0.x); a0.y = fmaf(s0.y, sw, a0.y);
    a0.z = fmaf(s0.z, sw, a0.z); a0.w = fmaf(s0.w, sw, a0.w);
    a1.x = fmaf(s1.x, sw, a1.x); a1.y = fmaf(s1.y, sw, a1.y);
    a1.z = fmaf(s1.z, sw, a1.z); a1.w = fmaf(s1.w, sw, a1.w);

    const float4* cb4 = reinterpret_cast<const float4*>(cb);
    const float4* g4  = reinterpret_cast<const float4*>(gamma);
    const float4* bt4 = reinterpret_cast<const float4*>(beta);
    float4* hrow = reinterpret_cast<float4*>(h + (size_t)d * HID);

#pragma unroll
    for (int half = 0; half < 2; half++) {
        int c = lane + 32 * half;
        float4 a  = half ? a1 : a0;
        float4 b  = __ldg(&cb4[c]);
        float4 g  = __ldg(&g4[c]);
        float4 bt = __ldg(&bt4[c]);
        float4 hv = hrow[c];
        hv.x += fmaxf(fmaf(a.x + b.x, g.x, bt.x), 0.0f);
        hv.y += fmaxf(fmaf(a.y + b.y, g.y, bt.y), 0.0f);
        hv.z += fmaxf(fmaf(a.z + b.z, g.z, bt.z), 0.0f);
        hv.w += fmaxf(fmaf(a.w + b.w, g.w, bt.w), 0.0f);
        hrow[c] = hv;
    }
}

// ---------------- host launcher ---------------------------------------------
template<bool RELU, bool BIAS>
static void launch_gemm(const float* A, const float* B, const float* bias, float* C,
                        int M, int N, int K) {
    dim3 grid((N + 63) / 64, (M + 127) / 128);
    gemm_kernel<128, 64, 16, 8, 4, RELU, BIAS><<<grid, 256>>>(A, B, bias, C, M, N, K);
}

template<bool BIAS, bool RELU>
static void launch_mma_gemm(const float* A, const float* W, const float* bias, float* C,
                            int M, int N, int K) {
    cudaFuncSetAttribute(mma_gemm_kernel<BIAS, RELU>,
                         cudaFuncAttributeMaxDynamicSharedMemorySize, MMA_SMEM);
    dim3 grid((N + 127) / 128, (M + 127) / 128);
    mma_gemm_kernel<BIAS, RELU><<<grid, 256, MMA_SMEM>>>(A, W, bias, C, M, N, K);
}

extern "C" void kernel_launch(void* const* d_in, const int* in_sizes, int n_in,
                              void* d_out, int out_size)
{
    const float* x      = (const float*)d_in[0];
    const int*   e_raw  = (const int*)d_in[1];
    const float* embW   = (const float*)d_in[2];
    const float* embB   = (const float*)d_in[3];
    const float* convW  = (const float*)d_in[4];
    const float* convB  = (const float*)d_in[5];
    const float* gamma  = (const float*)d_in[6];
    const float* beta   = (const float*)d_in[7];
    const float* W0 = (const float*)d_in[8];
    const float* b0 = (const float*)d_in[9];
    const float* W1 = (const float*)d_in[10];
    const float* b1 = (const float*)d_in[11];
    const float* W2 = (const float*)d_in[12];
    const float* b2 = (const float*)d_in[13];
    const float* W3 = (const float*)d_in[14];
    const float* b3 = (const float*)d_in[15];
    float* out = (float*)d_out;

    const int N = N_NODES;
    const int E = in_sizes[1] / 2;

    float *h, *hw, *dinv, *selfw, *c1, *c2, *c3, *csr_w;
    int *src32, *dst32, *cnt, *ptr, *fill, *csr_src, *bsum;
    cudaGetSymbolAddress((void**)&h,       g_h);
    cudaGetSymbolAddress((void**)&hw,      g_hw);
    cudaGetSymbolAddress((void**)&dinv,    g_dinv);
    cudaGetSymbolAddress((void**)&selfw,   g_self);
    cudaGetSymbolAddress((void**)&c1,      g_c1);
    cudaGetSymbolAddress((void**)&c2,      g_c2);
    cudaGetSymbolAddress((void**)&c3,      g_c3);
    cudaGetSymbolAddress((void**)&src32,   g_src32);
    cudaGetSymbolAddress((void**)&dst32,   g_dst32);
    cudaGetSymbolAddress((void**)&cnt,     g_cnt);
    cudaGetSymbolAddress((void**)&ptr,     g_ptr);
    cudaGetSymbolAddress((void**)&fill,    g_fill);
    cudaGetSymbolAddress((void**)&csr_src, g_csr_src);
    cudaGetSymbolAddress((void**)&csr_w,   g_csr_w);
    cudaGetSymbolAddress((void**)&bsum,    g_bsum);

    int nb = (N + SCAN_B - 1) / SCAN_B;

    // launches 1-5: edge prep (embed placed at #6 so ncu -s 5 -c 1 captures it)
    detect_kernel<<<1, 256>>>(e_raw, 1024);
    convert_count_kernel<<<(E + 255) / 256, 256>>>(e_raw, src32, dst32, cnt, fill, E);
    norm_kernel<<<(N + 255) / 256, 256>>>(cnt, dinv, selfw, N);
    scan1_kernel<<<nb, SCAN_B>>>(cnt, ptr, bsum, N);
    scan2_kernel<<<1, 256>>>(bsum, nb);

    // launch 6: embed GEMM (independent of CSR build)
    launch_mma_gemm<true, false>(x, embW, embB, h, N, HID, 500);

    // finish CSR build
    scan3_kernel<<<nb + 1, SCAN_B>>>(ptr, bsum, N, E);
    csr_fill_kernel<<<(E + 255) / 256, 256>>>(src32, dst32, ptr, fill, dinv, csr_src, csr_w, E);

    // GCN layers: tf32 tensor GEMM + fused aggregation/epilogue
    const int agg_blocks = (N + 7) / 8;
    for (int l = 0; l < 3; l++) {
        const float* Wl  = convW + (size_t)l * HID * HID;
        const float* cbl = convB + (size_t)l * HID;
        const float* gl  = gamma + (size_t)l * HID;
        const float* btl = beta  + (size_t)l * HID;

        launch_mma_gemm<false, false>(h, Wl, nullptr, hw, N, HID, HID);
        agg_kernel<<<agg_blocks, 256>>>(ptr, csr_src, csr_w, selfw, hw, cbl, gl, btl, h, N);
    }

    // classifier MLP: two tensor layers, tiny SIMT tail
    launch_mma_gemm<true, true>(h,  W0, b0, c1, N, 128, 256);
    launch_mma_gemm<true, true>(c1, W1, b1, c2, N, 64,  128);
    launch_gemm<true,  true>(c2, W2, b2, c3,  N, 32, 64);
    launch_gemm<false, true>(c3, W3, b3, out, N, 40, 32);
}

// round 7
// speedup vs baseline: 3.8233x; 1.1433x over previous
#include <cuda_runtime.h>
#include <cuda_fp16.h>
#include <stdint.h>

#define N_NODES 100000
#define N_EDGES 1600000
#define HID 256
#define SCAN_B 1024

// ---------------- scratch (device globals; no allocation allowed) ----------
__device__ float  g_h[(size_t)N_NODES * HID];
__device__ __half g_hw[(size_t)N_NODES * HID];   // fp16: halves agg gather bytes
__device__ float  g_dinv[N_NODES];
__device__ float  g_self[N_NODES];
__device__ float  g_c1[(size_t)N_NODES * 128];
__device__ float  g_c2[(size_t)N_NODES * 64];
__device__ float  g_c3[(size_t)N_NODES * 32];
__device__ int    g_src32[N_EDGES];
__device__ int    g_dst32[N_EDGES];
__device__ int    g_cnt[N_NODES];
__device__ int    g_ptr[N_NODES + 1];
__device__ int    g_fill[N_NODES];
__device__ int    g_csr_src[N_EDGES];
__device__ float  g_csr_w[N_EDGES];
__device__ int    g_bsum[(N_NODES + SCAN_B - 1) / SCAN_B + 1];
__device__ int    g_is64;

__device__ __forceinline__ uint32_t f2tf32(float f) {
    uint32_t o;
    asm("cvt.rna.tf32.f32 %0, %1;" : "=r"(o) : "f"(f));
    return o;
}
__device__ __forceinline__ uint32_t smem_u32(const void* p) {
    uint32_t a;
    asm("{ .reg .u64 t; cvta.to.shared.u64 t, %1; cvt.u32.u64 %0, t; }" : "=r"(a) : "l"(p));
    return a;
}
__device__ __forceinline__ void cp16(uint32_t dst, const void* src, int valid_bytes) {
    asm volatile("cp.async.ca.shared.global [%0], [%1], 16, %2;"
                 :: "r"(dst), "l"(src), "r"(valid_bytes) : "memory");
}
#define CP_COMMIT() asm volatile("cp.async.commit_group;" ::: "memory")
#define CP_WAIT(n)  asm volatile("cp.async.wait_group %0;" :: "n"(n) : "memory")

// =================== tf32 mma.sync GEMM, cp.async 2-stage pipeline ==========
#define ASTR 36
#define BSTR 136
#define ASZ  (128 * ASTR)
#define BSZ  (32 * BSTR)
#define STG  (ASZ + BSZ)
#define MMA_SMEM (2 * STG * 4)

template<bool BIAS, bool RELU, bool HALF_OUT>
__global__ void __launch_bounds__(256) mma_gemm_kernel(
    const float* __restrict__ A, const float* __restrict__ W,
    const float* __restrict__ bias, void* __restrict__ Cv,
    int M, int N, int K)
{
    extern __shared__ float sm[];
    const uint32_t sbase = smem_u32(sm);

    const int tid    = threadIdx.x;
    const int wid    = tid >> 5;
    const int lane   = tid & 31;
    const int gid    = lane >> 2;
    const int t4     = lane & 3;
    const int warp_m = wid >> 2;
    const int warp_n = wid & 3;
    const int row0   = blockIdx.y * 128;
    const int col0   = blockIdx.x * 128;

    float acc[4][4][4];
#pragma unroll
    for (int mt = 0; mt < 4; mt++)
#pragma unroll
        for (int nt = 0; nt < 4; nt++)
#pragma unroll
            for (int q = 0; q < 4; q++) acc[mt][nt][q] = 0.0f;

    const int n_chunks = (K + 31) / 32;

    auto load_chunk = [&](int ch, int st) {
        const int k0 = ch * 32;
        const uint32_t s0 = sbase + (uint32_t)(st * STG) * 4u;
#pragma unroll
        for (int t = 0; t < 4; t++) {
            int i  = tid + t * 256;
            int r  = i >> 3;
            int c4 = (i & 7) * 4;
            int gr = row0 + r, gk = k0 + c4;
            int valid = 0;
            if (gr < M) {
                int rem = (K - gk) * 4;
                valid = rem > 16 ? 16 : (rem > 0 ? rem : 0);
            }
            const float* p = valid ? (A + (size_t)gr * K + gk) : A;
            cp16(s0 + (uint32_t)(r * ASTR + c4) * 4u, p, valid);
        }
#pragma unroll
        for (int t = 0; t < 4; t++) {
            int i  = tid + t * 256;
            int k  = i >> 5;
            int n4 = (i & 31) * 4;
            int gk = k0 + k, gn = col0 + n4;
            int valid = (gk < K && gn < N) ? 16 : 0;
            const float* p = valid ? (W + (size_t)gk * N + gn) : W;
            cp16(s0 + (uint32_t)(ASZ + k * BSTR + n4) * 4u, p, valid);
        }
        CP_COMMIT();
    };

    load_chunk(0, 0);

    for (int ch = 0; ch < n_chunks; ch++) {
        if (ch + 1 < n_chunks) {
            load_chunk(ch + 1, (ch + 1) & 1);
            CP_WAIT(1);
        } else {
            CP_WAIT(0);
        }
        __syncthreads();

        const float* As = sm + (ch & 1) * STG;
        const float* Bs = As + ASZ;
#pragma unroll
        for (int ks = 0; ks < 4; ks++) {
            const int kb = ks * 8;
            uint32_t a[4][4], b[4][2];
#pragma unroll
            for (int mt = 0; mt < 4; mt++) {
                int r = warp_m * 64 + mt * 16 + gid;
                a[mt][0] = f2tf32(As[r * ASTR + kb + t4]);
                a[mt][1] = f2tf32(As[(r + 8) * ASTR + kb + t4]);
                a[mt][2] = f2tf32(As[r * ASTR + kb + t4 + 4]);
                a[mt][3] = f2tf32(As[(r + 8) * ASTR + kb + t4 + 4]);
            }
#pragma unroll
            for (int nt = 0; nt < 4; nt++) {
                int c = warp_n * 32 + nt * 8 + gid;
                b[nt][0] = f2tf32(Bs[(kb + t4) * BSTR + c]);
                b[nt][1] = f2tf32(Bs[(kb + t4 + 4) * BSTR + c]);
            }
#pragma unroll
            for (int mt = 0; mt < 4; mt++)
#pragma unroll
                for (int nt = 0; nt < 4; nt++) {
                    asm volatile(
                        "mma.sync.aligned.m16n8k8.row.col.f32.tf32.tf32.f32 "
                        "{%0,%1,%2,%3}, {%4,%5,%6,%7}, {%8,%9}, {%0,%1,%2,%3};"
                        : "+f"(acc[mt][nt][0]), "+f"(acc[mt][nt][1]),
                          "+f"(acc[mt][nt][2]), "+f"(acc[mt][nt][3])
                        : "r"(a[mt][0]), "r"(a[mt][1]), "r"(a[mt][2]), "r"(a[mt][3]),
                          "r"(b[nt][0]), "r"(b[nt][1]));
                }
        }
        __syncthreads();
    }

    // epilogue
#pragma unroll
    for (int mt = 0; mt < 4; mt++) {
#pragma unroll
        for (int half = 0; half < 2; half++) {
            int gr = row0 + warp_m * 64 + mt * 16 + gid + half * 8;
            if (gr >= M) continue;
#pragma unroll
            for (int nt = 0; nt < 4; nt++) {
                int gc = col0 + warp_n * 32 + nt * 8 + t4 * 2;
                if (gc >= N) continue;
                float2 o;
                o.x = acc[mt][nt][half * 2 + 0];
                o.y = acc[mt][nt][half * 2 + 1];
                if (BIAS) {
                    o.x += __ldg(&bias[gc]);
                    o.y += __ldg(&bias[gc + 1]);
                }
                if (RELU) {
                    o.x = fmaxf(o.x, 0.0f);
                    o.y = fmaxf(o.y, 0.0f);
                }
                if (HALF_OUT) {
                    *reinterpret_cast<__half2*>((__half*)Cv + (size_t)gr * N + gc) =
                        __floats2half2_rn(o.x, o.y);
                } else {
                    *reinterpret_cast<float2*>((float*)Cv + (size_t)gr * N + gc) = o;
                }
            }
        }
    }
}

// ---------------- edge dtype detection + conversion -------------------------
__global__ void detect_kernel(const int* __restrict__ e_raw, int n_check) {
    __shared__ int nz;
    if (threadIdx.x == 0) nz = 0;
    __syncthreads();
    for (int i = threadIdx.x; i < n_check; i += blockDim.x)
        if (e_raw[2 * i + 1] != 0) atomicAdd(&nz, 1);
    __syncthreads();
    if (threadIdx.x == 0) g_is64 = (nz == 0) ? 1 : 0;
}

__global__ void convert_count_kernel(const int* __restrict__ e_raw,
                                     int* __restrict__ src32, int* __restrict__ dst32,
                                     int* __restrict__ cnt, int* __restrict__ fill, int E) {
    int i = blockIdx.x * blockDim.x + threadIdx.x;
    if (i < N_NODES) { cnt[i] = 0; fill[i] = 0; }
    if (i >= E) return;
    int s, d;
    if (g_is64) { s = e_raw[2 * i]; d = e_raw[2 * (E + i)]; }
    else        { s = e_raw[i];     d = e_raw[E + i]; }
    src32[i] = s;
    dst32[i] = d;
    atomicAdd(&cnt[d], 1);
}

__global__ void norm_kernel(const int* __restrict__ cnt,
                            float* __restrict__ dinv, float* __restrict__ selfw, int n) {
    int i = blockIdx.x * blockDim.x + threadIdx.x;
    if (i < n) {
        float d = (float)cnt[i] + 1.0f;
        dinv[i]  = rsqrtf(d);
        selfw[i] = 1.0f / d;
    }
}

// ---------------- exclusive scan of cnt -> ptr ------------------------------
__global__ void scan1_kernel(const int* __restrict__ cnt, int* __restrict__ ptr,
                             int* __restrict__ bsum, int n) {
    __shared__ int sh[SCAN_B];
    int b = blockIdx.x;
    int i = b * SCAN_B + threadIdx.x;
    int v = (i < n) ? cnt[i] : 0;
    sh[threadIdx.x] = v;
    __syncthreads();
    for (int off = 1; off < SCAN_B; off <<= 1) {
        int t = (threadIdx.x >= off) ? sh[threadIdx.x - off] : 0;
        __syncthreads();
        sh[threadIdx.x] += t;
        __syncthreads();
    }
    if (i < n) ptr[i] = sh[threadIdx.x] - v;
    if (threadIdx.x == SCAN_B - 1) bsum[b] = sh[SCAN_B - 1];
}

__global__ void scan2_kernel(int* __restrict__ bsum, int nb) {
    __shared__ int sh[256];
    int v = (threadIdx.x < nb) ? bsum[threadIdx.x] : 0;
    sh[threadIdx.x] = v;
    __syncthreads();
    for (int off = 1; off < 256; off <<= 1) {
        int t = (threadIdx.x >= off) ? sh[threadIdx.x - off] : 0;
        __syncthreads();
        sh[threadIdx.x] += t;
        __syncthreads();
    }
    if (threadIdx.x < nb) bsum[threadIdx.x] = sh[threadIdx.x] - v;
}

__global__ void scan3_kernel(int* __restrict__ ptr, const int* __restrict__ bsum,
                             int n, int E) {
    int i = blockIdx.x * SCAN_B + threadIdx.x;
    if (i < n) ptr[i] += bsum[blockIdx.x];
    if (i == n) ptr[n] = E;
}

__global__ void csr_fill_kernel(const int* __restrict__ src, const int* __restrict__ dst,
                                const int* __restrict__ ptr, int* __restrict__ fill,
                                const float* __restrict__ dinv,
                                int* __restrict__ csr_src, float* __restrict__ csr_w, int E) {
    int i = blockIdx.x * blockDim.x + threadIdx.x;
    if (i >= E) return;
    int s = src[i], d = dst[i];
    int pos = atomicAdd(&fill[d], 1);
    int idx = ptr[d] + pos;
    csr_src[idx] = s;
    csr_w[idx] = dinv[s] * dinv[d];
}

// ---------------- SIMT GEMM (small classifier tail) --------------------------
template<int BM, int BN, int BK, int TM, int TN, bool RELU, bool BIAS>
__global__ void gemm_kernel(const float* __restrict__ A, const float* __restrict__ B,
                            const float* __restrict__ bias, float* __restrict__ C,
                            int M, int N, int K)
{
    constexpr int THREADS = (BM / TM) * (BN / TN);
    __shared__ float As[BK][BM];
    __shared__ float Bs[BK][BN];

    const int tid = threadIdx.x;
    const int tx  = tid % (BN / TN);
    const int ty  = tid / (BN / TN);
    const int row0 = blockIdx.y * BM;
    const int col0 = blockIdx.x * BN;

    float acc[TM][TN];
#pragma unroll
    for (int i = 0; i < TM; i++)
#pragma unroll
        for (int j = 0; j < TN; j++) acc[i][j] = 0.0f;

    for (int k0 = 0; k0 < K; k0 += BK) {
#pragma unroll 4
        for (int i = tid; i < BM * BK; i += THREADS) {
            int r = i / BK, c = i % BK;
            int gr = row0 + r, gc = k0 + c;
            As[c][r] = (gr < M && gc < K) ? A[(size_t)gr * K + gc] : 0.0f;
        }
#pragma unroll 4
        for (int i = tid; i < BK * BN; i += THREADS) {
            int r = i / BN, c = i % BN;
            int gk = k0 + r, gc = col0 + c;
            Bs[r][c] = (gk < K && gc < N) ? B[(size_t)gk * N + gc] : 0.0f;
        }
        __syncthreads();
#pragma unroll
        for (int kk = 0; kk < BK; kk++) {
            float a[TM], b[TN];
#pragma unroll
            for (int i = 0; i < TM; i++) a[i] = As[kk][ty * TM + i];
#pragma unroll
            for (int j = 0; j < TN; j++) b[j] = Bs[kk][tx * TN + j];
#pragma unroll
            for (int i = 0; i < TM; i++)
#pragma unroll
                for (int j = 0; j < TN; j++)
                    acc[i][j] = fmaf(a[i], b[j], acc[i][j]);
        }
        __syncthreads();
    }

#pragma unroll
    for (int i = 0; i < TM; i++) {
        int gr = row0 + ty * TM + i;
        if (gr >= M) continue;
#pragma unroll
        for (int j = 0; j < TN; j++) {
            int gc = col0 + tx * TN + j;
            if (gc >= N) continue;
            float v = acc[i][j];
            if (BIAS) v += bias[gc];
            if (RELU) v = fmaxf(v, 0.0f);
            C[(size_t)gr * N + gc] = v;
        }
    }
}

// ---------------- fused aggregation + BN + ReLU + residual ------------------
// warp per destination node; hw is fp16: one LDG.128 (8 halves) per lane per row.
__global__ void agg_kernel(const int* __restrict__ ptr,
                           const int* __restrict__ csr_src,
                           const float* __restrict__ csr_w,
                           const float* __restrict__ selfw,
                           const __half* __restrict__ hw,
                           const float* __restrict__ cb,
                           const float* __restrict__ gamma,
                           const float* __restrict__ beta,
                           float* __restrict__ h, int N)
{
    int d = blockIdx.x * 8 + (threadIdx.x >> 5);
    if (d >= N) return;
    int lane = threadIdx.x & 31;

    float acc[8];
#pragma unroll
    for (int q = 0; q < 8; q++) acc[q] = 0.0f;

    int beg = __ldg(&ptr[d]);
    int end = __ldg(&ptr[d + 1]);
    for (int j = beg; j < end; j++) {
        int s = __ldg(&csr_src[j]);
        float w = __ldg(&csr_w[j]);
        uint4 v = __ldg(reinterpret_cast<const uint4*>(hw + (size_t)s * HID) + lane);
        const __half2* p = reinterpret_cast<const __half2*>(&v);
#pragma unroll
        for (int q = 0; q < 4; q++) {
            float2 f = __half22float2(p[q]);
            acc[2 * q]     = fmaf(f.x, w, acc[2 * q]);
            acc[2 * q + 1] = fmaf(f.y, w, acc[2 * q + 1]);
        }
    }

    // self loop
    float sw = __ldg(&selfw[d]);
    uint4 v = __ldg(reinterpret_cast<const uint4*>(hw + (size_t)d * HID) + lane);
    const __half2* p = reinterpret_cast<const __half2*>(&v);
#pragma unroll
    for (int q = 0; q < 4; q++) {
        float2 f = __half22float2(p[q]);
        acc[2 * q]     = fmaf(f.x, sw, acc[2 * q]);
        acc[2 * q + 1] = fmaf(f.y, sw, acc[2 * q + 1]);
    }

    // epilogue: cols [8*lane, 8*lane+8)
    const float4* cb4 = reinterpret_cast<const float4*>(cb);
    const float4* g4  = reinterpret_cast<const float4*>(gamma);
    const float4* bt4 = reinterpret_cast<const float4*>(beta);
    float4* hrow = reinterpret_cast<float4*>(h + (size_t)d * HID);

#pragma unroll
    for (int q2 = 0; q2 < 2; q2++) {
        int c4i = lane * 2 + q2;
        float4 b  = __ldg(&cb4[c4i]);
        float4 g  = __ldg(&g4[c4i]);
        float4 bt = __ldg(&bt4[c4i]);
        float4 hv = hrow[c4i];
        hv.x += fmaxf(fmaf(acc[q2 * 4 + 0] + b.x, g.x, bt.x), 0.0f);
        hv.y += fmaxf(fmaf(acc[q2 * 4 + 1] + b.y, g.y, bt.y), 0.0f);
        hv.z += fmaxf(fmaf(acc[q2 * 4 + 2] + b.z, g.z, bt.z), 0.0f);
        hv.w += fmaxf(fmaf(acc[q2 * 4 + 3] + b.w, g.w, bt.w), 0.0f);
        hrow[c4i] = hv;
    }
}

// ---------------- host launcher ---------------------------------------------
template<bool RELU, bool BIAS>
static void launch_gemm(const float* A, const float* B, const float* bias, float* C,
                        int M, int N, int K) {
    dim3 grid((N + 63) / 64, (M + 127) / 128);
    gemm_kernel<128, 64, 16, 8, 4, RELU, BIAS><<<grid, 256>>>(A, B, bias, C, M, N, K);
}

template<bool BIAS, bool RELU, bool HALF_OUT>
static void launch_mma_gemm(const float* A, const float* W, const float* bias, void* C,
                            int M, int N, int K) {
    cudaFuncSetAttribute(mma_gemm_kernel<BIAS, RELU, HALF_OUT>,
                         cudaFuncAttributeMaxDynamicSharedMemorySize, MMA_SMEM);
    dim3 grid((N + 127) / 128, (M + 127) / 128);
    mma_gemm_kernel<BIAS, RELU, HALF_OUT><<<grid, 256, MMA_SMEM>>>(A, W, bias, C, M, N, K);
}

extern "C" void kernel_launch(void* const* d_in, const int* in_sizes, int n_in,
                              void* d_out, int out_size)
{
    const float* x      = (const float*)d_in[0];
    const int*   e_raw  = (const int*)d_in[1];
    const float* embW   = (const float*)d_in[2];
    const float* embB   = (const float*)d_in[3];
    const float* convW  = (const float*)d_in[4];
    const float* convB  = (const float*)d_in[5];
    const float* gamma  = (const float*)d_in[6];
    const float* beta   = (const float*)d_in[7];
    const float* W0 = (const float*)d_in[8];
    const float* b0 = (const float*)d_in[9];
    const float* W1 = (const float*)d_in[10];
    const float* b1 = (const float*)d_in[11];
    const float* W2 = (const float*)d_in[12];
    const float* b2 = (const float*)d_in[13];
    const float* W3 = (const float*)d_in[14];
    const float* b3 = (const float*)d_in[15];
    float* out = (float*)d_out;

    const int N = N_NODES;
    const int E = in_sizes[1] / 2;

    float *h, *dinv, *selfw, *c1, *c2, *c3, *csr_w;
    __half* hw;
    int *src32, *dst32, *cnt, *ptr, *fill, *csr_src, *bsum;
    cudaGetSymbolAddress((void**)&h,       g_h);
    cudaGetSymbolAddress((void**)&hw,      g_hw);
    cudaGetSymbolAddress((void**)&dinv,    g_dinv);
    cudaGetSymbolAddress((void**)&selfw,   g_self);
    cudaGetSymbolAddress((void**)&c1,      g_c1);
    cudaGetSymbolAddress((void**)&c2,      g_c2);
    cudaGetSymbolAddress((void**)&c3,      g_c3);
    cudaGetSymbolAddress((void**)&src32,   g_src32);
    cudaGetSymbolAddress((void**)&dst32,   g_dst32);
    cudaGetSymbolAddress((void**)&cnt,     g_cnt);
    cudaGetSymbolAddress((void**)&ptr,     g_ptr);
    cudaGetSymbolAddress((void**)&fill,    g_fill);
    cudaGetSymbolAddress((void**)&csr_src, g_csr_src);
    cudaGetSymbolAddress((void**)&csr_w,   g_csr_w);
    cudaGetSymbolAddress((void**)&bsum,    g_bsum);

    int nb = (N + SCAN_B - 1) / SCAN_B;

    // edge prep + CSR build
    detect_kernel<<<1, 256>>>(e_raw, 1024);
    convert_count_kernel<<<(E + 255) / 256, 256>>>(e_raw, src32, dst32, cnt, fill, E);
    norm_kernel<<<(N + 255) / 256, 256>>>(cnt, dinv, selfw, N);
    scan1_kernel<<<nb, SCAN_B>>>(cnt, ptr, bsum, N);
    scan2_kernel<<<1, 256>>>(bsum, nb);

    // embed GEMM (independent of CSR build)
    launch_mma_gemm<true, false, false>(x, embW, embB, h, N, HID, 500);

    scan3_kernel<<<nb + 1, SCAN_B>>>(ptr, bsum, N, E);
    csr_fill_kernel<<<(E + 255) / 256, 256>>>(src32, dst32, ptr, fill, dinv, csr_src, csr_w, E);

    // GCN layers: tf32 tensor GEMM (fp16 out) + fused aggregation/epilogue
    const int agg_blocks = (N + 7) / 8;
    for (int l = 0; l < 3; l++) {
        const float* Wl  = convW + (size_t)l * HID * HID;
        const float* cbl = convB + (size_t)l * HID;
        const float* gl  = gamma + (size_t)l * HID;
        const float* btl = beta  + (size_t)l * HID;

        launch_mma_gemm<false, false, true>(h, Wl, nullptr, hw, N, HID, HID);
        agg_kernel<<<agg_blocks, 256>>>(ptr, csr_src, csr_w, selfw, hw, cbl, gl, btl, h, N);
    }

    // classifier MLP
    launch_mma_gemm<true, true, false>(h,  W0, b0, c1, N, 128, 256);
    launch_mma_gemm<true, true, false>(c1, W1, b1, c2, N, 64,  128);
    launch_gemm<true,  true>(c2, W2, b2, c3,  N, 32, 64);
    launch_gemm<false, true>(c3, W3, b3, out, N, 40, 32);
}